// round 4
// baseline (speedup 1.0000x reference)
#include <cuda_runtime.h>

#define N_TRIALS   8
#define T_MS       2500
#define N_NEURONS  16000
#define N_SAMPLES  50
#define K_MAX      160
#define N_BINS     20
#define SYNC_COST  10.0f
#define EPS_F      1e-7f

// round(logspace(-3,0,20)*1000), matching numpy exactly
__constant__ int c_bins[N_BINS] = {1,1,2,3,4,6,9,13,18,26,38,55,78,113,162,234,336,483,695,1000};

// scratch (no allocations allowed -> __device__ globals)
__device__ float g_sel[N_SAMPLES * T_MS];          // 500 KB
__device__ float g_fano_parts[N_BINS * N_SAMPLES]; // per-(bin,sample) fano

// ---------------------------------------------------------------------------
// Kernel 1: sel[s][t] = sum_{k<cnt[s]} spikes[trial[s], t, idx[s][k]]
// grid: (ceil(T/128), N_SAMPLES), block 128. Lanes = consecutive t; every
// gather load is an isolated 32B sector (random neuron indices), so the shape
// targets high per-thread MLP (8 independent accumulators).
// ---------------------------------------------------------------------------
__global__ void __launch_bounds__(128) sel_kernel(const float* __restrict__ spikes,
                                                  const int*   __restrict__ trials,
                                                  const int*   __restrict__ idx,
                                                  const int*   __restrict__ counts)
{
    const int s = blockIdx.y;
    __shared__ int sidx[K_MAX];
    __shared__ int s_cnt;
    __shared__ int s_trial;

    if (threadIdx.x == 0) {
        s_cnt   = counts[s];
        s_trial = trials[s];
    }
    for (int k = threadIdx.x; k < K_MAX; k += blockDim.x)
        sidx[k] = idx[s * K_MAX + k];
    __syncthreads();

    const int t = blockIdx.x * blockDim.x + threadIdx.x;
    if (t >= T_MS) return;

    const long long base = (long long)s_trial * (long long)(T_MS) * (long long)(N_NEURONS)
                         + (long long)t * (long long)N_NEURONS;
    const float* __restrict__ row = spikes + base;
    const int cnt = s_cnt;

    // 8 independent accumulators -> 8 in-flight sector loads per thread
    float a0=0.f,a1=0.f,a2=0.f,a3=0.f,a4=0.f,a5=0.f,a6=0.f,a7=0.f;
    int k = 0;
    for (; k + 8 <= cnt; k += 8) {
        a0 += row[sidx[k+0]];
        a1 += row[sidx[k+1]];
        a2 += row[sidx[k+2]];
        a3 += row[sidx[k+3]];
        a4 += row[sidx[k+4]];
        a5 += row[sidx[k+5]];
        a6 += row[sidx[k+6]];
        a7 += row[sidx[k+7]];
    }
    float sum = ((a0+a1)+(a2+a3)) + ((a4+a5)+(a6+a7));
    for (; k < cnt; k++) sum += row[sidx[k]];

    // values are exact small integers in fp32 -> order-independent, exact
    g_sel[s * T_MS + t] = sum;
}

// ---------------------------------------------------------------------------
// Kernel 2: per (bin, sample) fano = var(binsums)/max(mean(binsums), eps)
// grid: (N_BINS, N_SAMPLES), block 128. Two-pass variance, deterministic tree
// reductions (no atomics).
// ---------------------------------------------------------------------------
__device__ __forceinline__ float block_reduce_128(float v, float* sh)
{
    const int tid = threadIdx.x;
    sh[tid] = v;
    __syncthreads();
    #pragma unroll
    for (int off = 64; off > 0; off >>= 1) {
        if (tid < off) sh[tid] += sh[tid + off];
        __syncthreads();
    }
    float r = sh[0];
    __syncthreads();
    return r;
}

__global__ void __launch_bounds__(128) fano_kernel()
{
    const int b  = blockIdx.x;
    const int s  = blockIdx.y;
    const int bs = c_bins[b];
    const int nb = T_MS / bs;

    __shared__ float binsum[T_MS];  // nb <= 2500 (10 KB)
    __shared__ float red[128];

    const float* __restrict__ row = g_sel + s * T_MS;

    // bin sums (exact integers)
    for (int j = threadIdx.x; j < nb; j += blockDim.x) {
        const int base = j * bs;
        float b0=0.f, b1=0.f, b2=0.f, b3=0.f;
        int i = 0;
        for (; i + 4 <= bs; i += 4) {
            b0 += row[base + i + 0];
            b1 += row[base + i + 1];
            b2 += row[base + i + 2];
            b3 += row[base + i + 3];
        }
        float acc = (b0+b1)+(b2+b3);
        for (; i < bs; i++) acc += row[base + i];
        binsum[j] = acc;
    }
    __syncthreads();

    // pass 1: mean
    float part = 0.f;
    for (int j = threadIdx.x; j < nb; j += blockDim.x) part += binsum[j];
    const float total = block_reduce_128(part, red);
    const float mean  = total / (float)nb;

    // pass 2: variance (mean of squared deviations, ddof=0)
    float part2 = 0.f;
    for (int j = threadIdx.x; j < nb; j += blockDim.x) {
        const float d = binsum[j] - mean;
        part2 += d * d;
    }
    const float ssq = block_reduce_128(part2, red);
    const float var = ssq / (float)nb;

    if (threadIdx.x == 0) {
        const float denom = fmaxf(mean, EPS_F);
        g_fano_parts[b * N_SAMPLES + s] = var / denom;
    }
}

// ---------------------------------------------------------------------------
// Kernel 3: fanos[b] = mean_s parts[b][s]; loss = 10 * mean_b (exp-fano)^2
// single warp, deterministic.
// ---------------------------------------------------------------------------
__global__ void loss_kernel(const float* __restrict__ exp_fanos,
                            float* __restrict__ out)
{
    const int tid = threadIdx.x;
    float v = 0.f;
    if (tid < N_BINS) {
        float fsum = 0.f;
        #pragma unroll 1
        for (int s = 0; s < N_SAMPLES; s++)
            fsum += g_fano_parts[tid * N_SAMPLES + s];
        const float fano = fsum / (float)N_SAMPLES;
        const float d = exp_fanos[tid] - fano;
        v = d * d;
    }
    #pragma unroll
    for (int off = 16; off > 0; off >>= 1)
        v += __shfl_down_sync(0xFFFFFFFFu, v, off);
    if (tid == 0)
        out[0] = SYNC_COST * (v / (float)N_BINS);
}

// ---------------------------------------------------------------------------
extern "C" void kernel_launch(void* const* d_in, const int* in_sizes, int n_in,
                              void* d_out, int out_size)
{
    const float* spikes    = (const float*)d_in[0];
    const float* exp_fanos = (const float*)d_in[1];
    const int*   trials    = (const int*)  d_in[2];
    const int*   idx       = (const int*)  d_in[3];
    const int*   counts    = (const int*)  d_in[4];
    float*       out       = (float*)d_out;

    dim3 g1((T_MS + 127) / 128, N_SAMPLES);
    sel_kernel<<<g1, 128>>>(spikes, trials, idx, counts);

    dim3 g2(N_BINS, N_SAMPLES);
    fano_kernel<<<g2, 128>>>();

    loss_kernel<<<1, 32>>>(exp_fanos, out);
}